// round 13
// baseline (speedup 1.0000x reference)
#include <cuda_runtime.h>
#include <cuda.h>
#include <math.h>
#include <stdint.h>

// ---------------------------------------------------------------------------
// VectorQuantizerLinearSoft — tcgen05 3xTF32, TMA B-loads, 4-stage ring,
// register-pipelined A loads, early TMA issue (R13).
// ---------------------------------------------------------------------------

#if defined(__CUDA_ARCH_FEAT_SM103_ALL) || defined(__CUDA_ARCH_FEAT_SM100_ALL)
#define HAS_TC 1
#else
#define HAS_TC 0
#endif

constexpr int NB = 65536;
constexpr int ND = 256;
constexpr int NK = 1024;

constexpr size_t OFF_Q   = 0;
constexpr size_t OFF_VQ  = 16777216;
constexpr size_t OFF_ENT = 16777217;
constexpr size_t OFF_IDX = 16777218;
constexpr size_t OFF_HQ  = 16842754;   // only 8B-aligned
constexpr size_t OFF_P   = 33619970;   // only 8B-aligned
constexpr size_t OFF_CM  = 100728834;

// Scratch (device globals: no allocations allowed)
__device__ float g_G[(size_t)NB * NK];      // 256MB  lat @ emb^T
__device__ float g_eT[ND * NK];             // emb^T full precision (fallback)
__device__ float g_embI[(size_t)NK * 512];  // emb rows, [hi16|lo16] per 16-col block
__device__ float g_embTI[(size_t)ND * 2048];// emb^T rows, [hi16|lo16]
__device__ float g_ee[NK];                  // ||e_j||^2
__device__ float g_pavg[2048 * NK];         // per-soft-CTA colsums of probs
__device__ float g_pavg2[32 * NK];
__device__ float g_ploss[512];              // per-GEMM2-CTA sum (q-z)^2
__device__ float g_pmind[2048];             // per-soft-CTA sum min dist

// ---------------- generic helpers ----------------
__device__ __forceinline__ void cp16(void* smem, const void* gmem) {
    unsigned s = (unsigned)__cvta_generic_to_shared(smem);
    asm volatile("cp.async.cg.shared.global [%0], [%1], 16;\n" :: "r"(s), "l"(gmem));
}
__device__ __forceinline__ void cp_commit() { asm volatile("cp.async.commit_group;\n"); }
__device__ __forceinline__ void cp_wait1()  { asm volatile("cp.async.wait_group 1;\n"); }
__device__ __forceinline__ void cp_wait0()  { asm volatile("cp.async.wait_group 0;\n"); }

__device__ __forceinline__ float tf32hi(float x) {
    uint32_t u; asm("cvt.rna.tf32.f32 %0, %1;" : "=r"(u) : "f"(x));
    return __uint_as_float(u);
}
__device__ __forceinline__ uint32_t sw128(uint32_t off) { return off ^ ((off >> 3) & 0x70); }

// ---------------- tcgen05 / TMA helpers (accelerated pass only) ------------
#if HAS_TC
__device__ __forceinline__ uint32_t smem_u32(const void* p) {
    uint32_t a;
    asm("{ .reg .u64 t; cvta.to.shared.u64 t, %1; cvt.u32.u64 %0, t; }" : "=r"(a) : "l"(p));
    return a;
}
__device__ __forceinline__ uint32_t elect1() {
    uint32_t p;
    asm volatile("{ .reg .pred p; elect.sync _|p, 0xFFFFFFFF; selp.b32 %0, 1, 0, p; }" : "=r"(p));
    return p;
}
// SW128 K-major smem descriptor (SBO=64, LBO=1, layout SW128, Blackwell v1)
__device__ __forceinline__ uint64_t sdesc(uint32_t addr) {
    return 0x4000404000010000ULL | ((uint64_t)(addr >> 4) & 0x3FFF);
}
// idesc: dtype=F32, atype=btype=TF32(2), N=256, M=128, K-major both
constexpr uint32_t IDESC_TF32_N256 =
    (1u << 4) | (2u << 7) | (2u << 10) | ((256u / 8) << 17) | ((128u / 16) << 24);

__device__ __forceinline__ void mma_tf32(uint32_t d, uint64_t ad, uint64_t bd,
                                         uint32_t idesc, bool en) {
    uint32_t e = en ? 1u : 0u;
    asm volatile(
        "{\n\t.reg .pred p;\n\tsetp.ne.u32 p, %5, 0;\n\t"
        "tcgen05.mma.cta_group::1.kind::tf32 [%0], %1, %2, %3, {%4, %4, %4, %4}, p;\n\t}"
        :: "r"(d), "l"(ad), "l"(bd), "r"(idesc), "r"(0u), "r"(e) : "memory");
}

__device__ __forceinline__ void tma2d(uint32_t dst, const CUtensorMap* map,
                                      int x, int y, uint32_t mbar) {
    asm volatile(
        "cp.async.bulk.tensor.2d.shared::cta.global.tile.mbarrier::complete_tx::bytes "
        "[%0], [%1, {%2, %3}], [%4];"
        :: "r"(dst), "l"(map), "r"(x), "r"(y), "r"(mbar) : "memory");
}

#define FENCE_PROXY()     asm volatile("fence.proxy.async.shared::cta;" ::: "memory")
#define TC_ALLOC(sa, n)   asm volatile("tcgen05.alloc.cta_group::1.sync.aligned.shared::cta.b32 [%0], %1;" :: "r"(sa), "r"(n) : "memory")
#define TC_DEALLOC(t, n)  asm volatile("tcgen05.dealloc.cta_group::1.sync.aligned.b32 %0, %1;" :: "r"(t), "r"(n))
#define TC_COMMIT(mb)     asm volatile("tcgen05.commit.cta_group::1.mbarrier::arrive::one.shared::cluster.b64 [%0];" :: "r"(mb) : "memory")
#define TC_WAIT_LD()      asm volatile("tcgen05.wait::ld.sync.aligned;" ::: "memory")
#define TC_FENCE_AFTER()  asm volatile("tcgen05.fence::after_thread_sync;" ::: "memory")
#define TC_FENCE_BEFORE() asm volatile("tcgen05.fence::before_thread_sync;" ::: "memory")
#define MBAR_INIT(mb, c)  asm volatile("mbarrier.init.shared.b64 [%0], %1;" :: "r"(mb), "r"(c) : "memory")
#define MBAR_INVAL(mb)    asm volatile("mbarrier.inval.shared.b64 [%0];" :: "r"(mb) : "memory")
#define MBAR_EXPECT(mb, n) asm volatile("mbarrier.arrive.expect_tx.shared.b64 _, [%0], %1;" :: "r"(mb), "r"(n) : "memory")

#define MBAR_WAIT(mb, par) do {                                              \
    uint32_t _m = (mb), _p = (par), _d;                                      \
    asm volatile("{\n\t.reg .pred p;\n\t"                                    \
        "mbarrier.try_wait.parity.acquire.cta.shared::cta.b64 p, [%1], %2;\n\t" \
        "selp.b32 %0, 1, 0, p;\n\t}" : "=r"(_d) : "r"(_m), "r"(_p) : "memory"); \
    if (!_d) {                                                               \
        asm volatile("{\n\t.reg .pred P1;\n\t"                               \
            "WL_%=:\n\t"                                                     \
            "mbarrier.try_wait.parity.acquire.cta.shared::cta.b64 P1, [%0], %1, 0x989680;\n\t" \
            "@P1 bra.uni WD_%=;\n\t"                                         \
            "bra.uni WL_%=;\n\t"                                             \
            "WD_%=:\n\t}" :: "r"(_m), "r"(_p) : "memory");                   \
    }                                                                        \
} while (0)

#define LDTM32(r, a)                                                         \
    asm volatile("tcgen05.ld.sync.aligned.32x32b.x32.b32 "                   \
        "{%0,%1,%2,%3,%4,%5,%6,%7,%8,%9,%10,%11,%12,%13,%14,%15,"            \
        "%16,%17,%18,%19,%20,%21,%22,%23,%24,%25,%26,%27,%28,%29,%30,%31}, [%32];" \
        : "=r"((r)[0]), "=r"((r)[1]), "=r"((r)[2]), "=r"((r)[3]),            \
          "=r"((r)[4]), "=r"((r)[5]), "=r"((r)[6]), "=r"((r)[7]),            \
          "=r"((r)[8]), "=r"((r)[9]), "=r"((r)[10]), "=r"((r)[11]),          \
          "=r"((r)[12]), "=r"((r)[13]), "=r"((r)[14]), "=r"((r)[15]),        \
          "=r"((r)[16]), "=r"((r)[17]), "=r"((r)[18]), "=r"((r)[19]),        \
          "=r"((r)[20]), "=r"((r)[21]), "=r"((r)[22]), "=r"((r)[23]),        \
          "=r"((r)[24]), "=r"((r)[25]), "=r"((r)[26]), "=r"((r)[27]),        \
          "=r"((r)[28]), "=r"((r)[29]), "=r"((r)[30]), "=r"((r)[31])         \
        : "r"(a))
#endif  // HAS_TC

// sub-chunk descriptor offsets (16B units) within a [hi64B|lo64B] 128B row:
// terms: hiA*hiB (2 K-steps), loA*hiB (2), hiA*loB (2)
__device__ __constant__ int c_AO[6] = {0, 2, 4, 6, 0, 2};
__device__ __constant__ int c_BO[6] = {0, 2, 0, 2, 4, 6};

// ---------------- prep: interleaved split tables + row norms ---------------
__global__ void k_prep2(const float* __restrict__ emb) {
    int j = blockIdx.x;  // 0..1023
    int cb = j >> 4, tb = j & 15;
    for (int d = threadIdx.x; d < 256; d += 256) {
        float v = emb[(size_t)j * ND + d];
        float h = tf32hi(v);
        g_eT[(size_t)d * NK + j] = v;
        g_embTI[(size_t)d * 2048 + cb * 32 + tb]      = h;
        g_embTI[(size_t)d * 2048 + cb * 32 + 16 + tb] = __fsub_rn(v, h);
    }
    for (int t = threadIdx.x; t < 512; t += 256) {
        int c = t >> 5, u = t & 31;
        float v = emb[(size_t)j * ND + c * 16 + (u & 15)];
        float h = tf32hi(v);
        g_embI[(size_t)j * 512 + t] = (u < 16) ? h : __fsub_rn(v, h);
    }
}

__global__ void k_ee(const float* __restrict__ emb) {
    int warp = (blockIdx.x * blockDim.x + threadIdx.x) >> 5;
    int lane = threadIdx.x & 31;
    for (int rr = 0; rr < 32; ++rr) {
        int row = warp * 32 + rr;
        float s = 0.f;
#pragma unroll
        for (int k = 0; k < 8; ++k) {
            float v = emb[(size_t)row * ND + lane + 32 * k];
            s = fmaf(v, v, s);
        }
#pragma unroll
        for (int off = 16; off; off >>= 1) s += __shfl_xor_sync(0xffffffffu, s, off);
        if (lane == 0) g_ee[row] = s;
    }
}

// ---------------- profiler window shim (makes k_gemm1 launch #4) -----------
__global__ void k_nop() {}

// ---------------- GEMM kernels: stage = A(16K) + B(32K) = 48K, 4 stages ----
// smem: [0,4) tmem ptr, [8,40) mma bars, [40,72) tma bars, [80,112) red
constexpr int STG_SZ = 49152;
constexpr int G_SMEM = 1024 + 4 * STG_SZ;   // 197632
constexpr int MB_MMA = 8, MB_TMA = 40;

__global__ void __launch_bounds__(256, 1)
k_gemm1(const float* __restrict__ lat,
        const __grid_constant__ CUtensorMap tmB) {
#if HAS_TC
    extern __shared__ char smem[];
    uint32_t sbase = smem_u32(smem);
    const int tid = threadIdx.x, wid = tid >> 5;
    const int row0 = blockIdx.x * 128;

    if (wid == 0) TC_ALLOC(sbase, 512);
    if (tid == 0)
        for (int b = 0; b < 4; ++b) {
            MBAR_INIT(sbase + MB_MMA + b * 8, 1);
            MBAR_INIT(sbase + MB_TMA + b * 8, 1);
        }
    __syncthreads();
    uint32_t tmem;
    asm volatile("ld.shared.b32 %0, [%1];" : "=r"(tmem) : "r"(sbase));

    const float* latb = lat + (size_t)row0 * ND;

    // A-source loads for chunk gp (8 floats/thread into registers)
    auto prep_load = [&](int gp, float4* v) {
        int c = gp & 15;
#pragma unroll
        for (int it = 0; it < 2; ++it) {
            int t = tid + it * 256;
            int r = t >> 2, c4 = t & 3;
            v[it] = *(const float4*)(latb + (size_t)r * ND + c * 16 + c4 * 4);
        }
    };
    // split+STS into stage (A only)
    auto prep_storeA = [&](int gp, const float4* v) {
        char* st = smem + 1024 + (gp & 3) * STG_SZ;
#pragma unroll
        for (int it = 0; it < 2; ++it) {
            int t = tid + it * 256;
            int r = t >> 2, c4 = t & 3;
            float4 vv = v[it];
            float4 h = make_float4(tf32hi(vv.x), tf32hi(vv.y), tf32hi(vv.z), tf32hi(vv.w));
            float4 l = make_float4(__fsub_rn(vv.x, h.x), __fsub_rn(vv.y, h.y),
                                   __fsub_rn(vv.z, h.z), __fsub_rn(vv.w, h.w));
            *(float4*)(st + sw128(r * 128 + c4 * 16))      = h;
            *(float4*)(st + sw128(r * 128 + 64 + c4 * 16)) = l;
        }
        FENCE_PROXY();
    };
    auto issue_tma = [&](int gp) {
        if (tid == 0) {
            uint32_t mb = sbase + MB_TMA + (gp & 3) * 8;
            MBAR_EXPECT(mb, 32768u);
            tma2d(sbase + 1024 + (gp & 3) * STG_SZ + 16384, &tmB,
                  (gp & 15) * 32, (gp >> 4) * 256, mb);
        }
    };

    auto epilogue = [&](int q) {
        int wg = tid >> 7, w4 = (tid >> 5) & 3, lane = tid & 31;
        int row = row0 + w4 * 32 + lane;
        uint32_t dbase = tmem + (q & 1) * 256;
#pragma unroll 1
        for (int b = 0; b < 4; ++b) {
            uint32_t r[32];
            LDTM32(r, dbase + wg * 128 + b * 32);
            TC_WAIT_LD();
            float4* gp = (float4*)&g_G[(size_t)row * NK + q * 256 + wg * 128 + b * 32];
#pragma unroll
            for (int c4 = 0; c4 < 8; ++c4)
                gp[c4] = make_float4(__uint_as_float(r[c4 * 4 + 0]),
                                     __uint_as_float(r[c4 * 4 + 1]),
                                     __uint_as_float(r[c4 * 4 + 2]),
                                     __uint_as_float(r[c4 * 4 + 3]));
        }
    };

    {   // prologue: chunks 0, 1
        float4 v[2];
        prep_load(0, v); prep_storeA(0, v); issue_tma(0);
        prep_load(1, v); prep_storeA(1, v); issue_tma(1);
    }

    for (int g = 0; g < 64; ++g) {
        const bool doP = (g + 2 < 64);
        float4 pf[2];
        if (doP) prep_load(g + 2, pf);           // LDG latency hidden below
        MBAR_WAIT(sbase + MB_TMA + (g & 3) * 8, (uint32_t)((g >> 2) & 1));
        __syncthreads();
        int c = g & 15, p = g >> 4;
        if (wid == 0) {
            if (elect1()) {
                uint32_t sa = sbase + 1024 + (g & 3) * STG_SZ;
                uint64_t ad = sdesc(sa);
                uint64_t bd = sdesc(sa + 16384);
                uint32_t dt = tmem + (p & 1) * 256;
#pragma unroll
                for (int i = 0; i < 6; ++i)
                    mma_tf32(dt, ad + c_AO[i], bd + c_BO[i], IDESC_TF32_N256,
                             (c > 0) || (i > 0));
                TC_COMMIT(sbase + MB_MMA + (g & 3) * 8);
            }
        }
        if (g >= 2 && doP)
            MBAR_WAIT(sbase + MB_MMA + ((g - 2) & 3) * 8, (uint32_t)(((g - 2) >> 2) & 1));
        if (doP) issue_tma(g + 2);               // early TMA: max lead time
        if ((g & 15) == 1 && g >= 17) {  // mma(16q+15) waited at g=16q+17
            TC_FENCE_AFTER();
            epilogue((g >> 4) - 1);
            TC_FENCE_BEFORE();
        }
        if (doP) prep_storeA(g + 2, pf);
    }
    MBAR_WAIT(sbase + MB_MMA + (63 & 3) * 8, (uint32_t)((63 >> 2) & 1));
    TC_FENCE_AFTER();
    epilogue(3);
    TC_FENCE_BEFORE();
    __syncthreads();
    if (tid == 0)
        for (int b = 0; b < 4; ++b) {
            MBAR_INVAL(sbase + MB_MMA + b * 8);
            MBAR_INVAL(sbase + MB_TMA + b * 8);
        }
    __syncthreads();
    if (wid == 0) TC_DEALLOC(tmem, 512);
#else
    // ---------------- FFMA fallback (R4 GEMM1 structure) ----------------
    extern __shared__ float smf[];
    float* sZ = smf;
    float* sE = smf + 8192;
    const int tid = threadIdx.x, w = tid >> 5, lane = tid & 31;
    const int row0 = blockIdx.x * 128;

    for (int st = 0; st < 4; ++st) {
        const int r0 = row0 + st * 32;
        for (int i = tid; i < 4096; i += 256) cp16(sE + i * 4, g_eT + i * 4);
        cp_commit();
        for (int i = tid; i < 2048; i += 256)
            ((float4*)sZ)[i] = ((const float4*)(lat + (size_t)r0 * ND))[i];
        __syncthreads();

        float acc[4][32];
#pragma unroll
        for (int i = 0; i < 4; ++i)
#pragma unroll
            for (int j = 0; j < 32; ++j) acc[i][j] = 0.f;

#pragma unroll 1
        for (int ch = 0; ch < 16; ++ch) {
            if (ch < 15) {
                const float* src = g_eT + (size_t)(ch + 1) * 16 * NK;
                float* dst = sE + ((ch + 1) & 1) * 16384;
                for (int i = tid; i < 4096; i += 256) cp16(dst + i * 4, src + i * 4);
                cp_commit();
                cp_wait1();
            } else {
                cp_wait0();
            }
            __syncthreads();

            const float* bufp = sE + (ch & 1) * 16384;
            const float* zrow = sZ + (w * 4) * ND + ch * 16;
#pragma unroll 4
            for (int kk = 0; kk < 16; ++kk) {
                float z0 = zrow[kk];
                float z1 = zrow[256 + kk];
                float z2 = zrow[512 + kk];
                float z3 = zrow[768 + kk];
                const float* er = bufp + kk * NK + lane;
#pragma unroll
                for (int j = 0; j < 32; ++j) {
                    float ev = er[j * 32];
                    acc[0][j] = fmaf(z0, ev, acc[0][j]);
                    acc[1][j] = fmaf(z1, ev, acc[1][j]);
                    acc[2][j] = fmaf(z2, ev, acc[2][j]);
                    acc[3][j] = fmaf(z3, ev, acc[3][j]);
                }
            }
            __syncthreads();
        }
#pragma unroll
        for (int i = 0; i < 4; ++i) {
            float* gp = &g_G[(size_t)(r0 + w * 4 + i) * NK];
#pragma unroll
            for (int j = 0; j < 32; ++j) gp[lane + 32 * j] = acc[i][j];
        }
        __syncthreads();
    }
#endif
}

// ---------------- k_soft: dist/argmin(+exact refine)/softmax + partials ----
__global__ void __launch_bounds__(256, 2)
k_soft(const float* __restrict__ lat, const float* __restrict__ emb,
       float* __restrict__ out) {
    __shared__ float sX[8 * NK];
    __shared__ float s_mind[32];
    __shared__ int   s_idx[32];

    const int cta = blockIdx.x, row0 = cta * 32;
    const int tid = threadIdx.x, w = tid >> 5, lane = tid & 31;

    float csum[32];
#pragma unroll
    for (int j = 0; j < 32; ++j) csum[j] = 0.f;

#pragma unroll 1
    for (int i = 0; i < 4; ++i) {
        const int r = row0 + w * 4 + i;
        const float* zr = lat + (size_t)r * ND;

        float zz = 0.f;
#pragma unroll
        for (int k = 0; k < 8; ++k) { float v = zr[lane + 32 * k]; zz = fmaf(v, v, zz); }
#pragma unroll
        for (int off = 16; off; off >>= 1) zz += __shfl_xor_sync(0xffffffffu, zz, off);

        float g[32];
        const float* gr = g_G + (size_t)r * NK;
#pragma unroll
        for (int j = 0; j < 32; ++j) g[j] = gr[lane + 32 * j];

        float dmin = 3.4e38f;
#pragma unroll
        for (int j = 0; j < 32; ++j) {
            float ee = __ldg(&g_ee[lane + 32 * j]);
            float di = __fsub_rn(__fadd_rn(zz, ee), __fmul_rn(2.0f, g[j]));
            g[j] = di;
            dmin = fminf(dmin, di);
        }
#pragma unroll
        for (int off = 16; off; off >>= 1)
            dmin = fminf(dmin, __shfl_xor_sync(0xffffffffu, dmin, off));

        // exact-FFMA refinement of argmin (tensor dist error << 1e-4)
        {
            float thr = dmin + 1e-4f;
            float bd = 3.4e38f;
            int   bi = NK;
#pragma unroll 1
            for (int j = 0; j < 32; ++j) {
                unsigned m = __ballot_sync(0xffffffffu, g[j] < thr);
                while (m) {
                    int src = __ffs(m) - 1;
                    m &= m - 1;
                    int col = src + 32 * j;
                    const float* er = emb + (size_t)col * ND;
                    float s = 0.f;
#pragma unroll
                    for (int k = 0; k < 8; ++k)
                        s = fmaf(zr[lane + 32 * k], __ldg(&er[lane + 32 * k]), s);
#pragma unroll
                    for (int off = 16; off; off >>= 1)
                        s += __shfl_xor_sync(0xffffffffu, s, off);
                    float dc = __fsub_rn(__fadd_rn(zz, __ldg(&g_ee[col])),
                                         __fmul_rn(2.0f, s));
                    if (dc < bd) { bd = dc; bi = col; }
                }
            }
            if (lane == 0) { s_mind[w * 4 + i] = bd; s_idx[w * 4 + i] = bi; }
        }

        float ssum = 0.f;
#pragma unroll
        for (int j = 0; j < 32; ++j) {
            float pv = __expf(-10.0f * (g[j] - dmin));
            g[j] = pv;
            ssum += pv;
        }
#pragma unroll
        for (int off = 16; off; off >>= 1) ssum += __shfl_xor_sync(0xffffffffu, ssum, off);
        float rinv = 1.0f / ssum;
        float* pout = out + OFF_P + (size_t)r * NK;
#pragma unroll
        for (int j = 0; j < 32; ++j) {
            float p = g[j] * rinv;
            pout[lane + 32 * j] = p;
            csum[j] += p;
        }
    }

#pragma unroll
    for (int j = 0; j < 32; ++j) sX[w * NK + lane + 32 * j] = csum[j];
    __syncthreads();

    for (int c = tid; c < NK; c += 256) {
        float s = 0.f;
#pragma unroll
        for (int ww = 0; ww < 8; ++ww) s += sX[ww * NK + c];
        g_pavg[(size_t)cta * NK + c] = s;
    }
    if (tid == 0) {
        float s = 0.f;
        for (int r = 0; r < 32; ++r) s += s_mind[r];
        g_pmind[cta] = s;
    }
    if (tid < 32) out[OFF_IDX + row0 + tid] = (float)s_idx[tid];

    for (int i = tid; i < 32 * ND / 2; i += 256) {
        int r = i >> 7, d2 = i & 127;
        float2 v = ((const float2*)(emb + (size_t)s_idx[r] * ND))[d2];
        ((float2*)(out + OFF_HQ + (size_t)row0 * ND))[i] = v;
    }
}

// ---------------- GEMM2: Q = P @ emb (M=128/CTA, N=256, 64 K-blocks) -------
__global__ void __launch_bounds__(256, 1)
k_gemm2(const float* __restrict__ lat,
        const __grid_constant__ CUtensorMap tmB,
        const float* __restrict__ emb, float* __restrict__ out) {
    (void)emb;
#if HAS_TC
    extern __shared__ char smem[];
    uint32_t sbase = smem_u32(smem);
    const int tid = threadIdx.x, wid = tid >> 5;
    const int row0 = blockIdx.x * 128;

    if (wid == 0) TC_ALLOC(sbase, 512);
    if (tid == 0)
        for (int b = 0; b < 4; ++b) {
            MBAR_INIT(sbase + MB_MMA + b * 8, 1);
            MBAR_INIT(sbase + MB_TMA + b * 8, 1);
        }
    __syncthreads();
    uint32_t tmem;
    asm volatile("ld.shared.b32 %0, [%1];" : "=r"(tmem) : "r"(sbase));

    const float* pbase = out + OFF_P + (size_t)row0 * NK;

    auto prep_load = [&](int gp, float4* v) {
#pragma unroll
        for (int it = 0; it < 2; ++it) {
            int t = tid + it * 256;
            int r = t >> 2, c4 = t & 3;
            const float* src = pbase + (size_t)r * NK + gp * 16 + c4 * 4;
            float2 v01 = *(const float2*)(src);
            float2 v23 = *(const float2*)(src + 2);
            v[it] = make_float4(v01.x, v01.y, v23.x, v23.y);
        }
    };
    auto prep_storeA = [&](int gp, const float4* v) {
        char* st = smem + 1024 + (gp & 3) * STG_SZ;
#pragma unroll
        for (int it = 0; it < 2; ++it) {
            int t = tid + it * 256;
            int r = t >> 2, c4 = t & 3;
            float4 vv = v[it];
            float4 h = make_float4(tf32hi(vv.x), tf32hi(vv.y), tf32hi(vv.z), tf32hi(vv.w));
            float4 l = make_float4(__fsub_rn(vv.x, h.x), __fsub_rn(vv.y, h.y),
                                   __fsub_rn(vv.z, h.z), __fsub_rn(vv.w, h.w));
            *(float4*)(st + sw128(r * 128 + c4 * 16))      = h;
            *(float4*)(st + sw128(r * 128 + 64 + c4 * 16)) = l;
        }
        FENCE_PROXY();
    };
    auto issue_tma = [&](int gp) {
        if (tid == 0) {
            uint32_t mb = sbase + MB_TMA + (gp & 3) * 8;
            MBAR_EXPECT(mb, 32768u);
            tma2d(sbase + 1024 + (gp & 3) * STG_SZ + 16384, &tmB,
                  gp * 32, 0, mb);
        }
    };

    {   // prologue
        float4 v[2];
        prep_load(0, v); prep_storeA(0, v); issue_tma(0);
        prep_load(1, v); prep_storeA(1, v); issue_tma(1);
    }

    for (int g = 0; g < 64; ++g) {
        const bool doP = (g + 2 < 64);
        float4 pf[2];
        if (doP) prep_load(g + 2, pf);
        MBAR_WAIT(sbase + MB_TMA + (g & 3) * 8, (uint32_t)((g >> 2) & 1));
        __syncthreads();
        if (wid == 0) {
            if (elect1()) {
                uint32_t sa = sbase + 1024 + (g & 3) * STG_SZ;
                uint64_t ad = sdesc(sa);
                uint64_t bd = sdesc(sa + 16384);
#pragma unroll
                for (int i = 0; i < 6; ++i)
                    mma_tf32(tmem, ad + c_AO[i], bd + c_BO[i], IDESC_TF32_N256,
                             (g > 0) || (i > 0));
                TC_COMMIT(sbase + MB_MMA + (g & 3) * 8);
            }
        }
        if (g >= 2 && doP)
            MBAR_WAIT(sbase + MB_MMA + ((g - 2) & 3) * 8, (uint32_t)(((g - 2) >> 2) & 1));
        if (doP) issue_tma(g + 2);
        if (doP) prep_storeA(g + 2, pf);
    }
    MBAR_WAIT(sbase + MB_MMA + (63 & 3) * 8, (uint32_t)((63 >> 2) & 1));
    TC_FENCE_AFTER();

    // epilogue: D[128 lanes][256 cols] -> q, loss partial
    {
        int wg = tid >> 7, w4 = (tid >> 5) & 3, lane = tid & 31;
        int row = row0 + w4 * 32 + lane;
        float lp = 0.f;
#pragma unroll 1
        for (int b = 0; b < 4; ++b) {
            uint32_t r[32];
            LDTM32(r, tmem + wg * 128 + b * 32);
            TC_WAIT_LD();
            int cb = wg * 128 + b * 32;
            float4* qp = (float4*)(out + OFF_Q + (size_t)row * ND + cb);
            const float4* lt = (const float4*)(lat + (size_t)row * ND + cb);
#pragma unroll
            for (int c4 = 0; c4 < 8; ++c4) {
                float4 q = make_float4(__uint_as_float(r[c4 * 4 + 0]),
                                       __uint_as_float(r[c4 * 4 + 1]),
                                       __uint_as_float(r[c4 * 4 + 2]),
                                       __uint_as_float(r[c4 * 4 + 3]));
                float4 l = lt[c4];
                qp[c4] = q;
                float d0 = q.x - l.x, d1 = q.y - l.y, d2 = q.z - l.z, d3 = q.w - l.w;
                lp = fmaf(d0, d0, lp); lp = fmaf(d1, d1, lp);
                lp = fmaf(d2, d2, lp); lp = fmaf(d3, d3, lp);
            }
        }
        TC_FENCE_BEFORE();
#pragma unroll
        for (int off = 16; off; off >>= 1) lp += __shfl_xor_sync(0xffffffffu, lp, off);
        float* red = (float*)(smem + 80);
        if ((tid & 31) == 0) red[tid >> 5] = lp;
        __syncthreads();
        if (tid == 0) {
            float s = 0.f;
            for (int ww = 0; ww < 8; ++ww) s += red[ww];
            g_ploss[blockIdx.x] = s;
        }
    }
    if (tid == 0)
        for (int b = 0; b < 4; ++b) {
            MBAR_INVAL(sbase + MB_MMA + b * 8);
            MBAR_INVAL(sbase + MB_TMA + b * 8);
        }
    __syncthreads();
    if (wid == 0) TC_DEALLOC(tmem, 512);
#else
    // ---------------- FFMA fallback (R4 GEMM2 structure) ----------------
    extern __shared__ float smf[];
    float* sE  = smf;
    float* sPb = smf + 16384;
    __shared__ float red8[8];
    const int tid = threadIdx.x, w = tid >> 5, lane = tid & 31;
    const int row0 = blockIdx.x * 128;
    float lsum = 0.f;

    for (int st = 0; st < 4; ++st) {
        const int r0 = row0 + st * 32;
        const float* pbase = out + OFF_P + (size_t)r0 * NK;

        float qacc[4][8];
#pragma unroll
        for (int i = 0; i < 4; ++i)
#pragma unroll
            for (int m = 0; m < 8; ++m) qacc[i][m] = 0.f;

        for (int i = tid; i < 2048; i += 256) cp16(sE + i * 4, emb + i * 4);
        cp_commit();

#pragma unroll 1
        for (int ch = 0; ch < 32; ++ch) {
            if (ch < 31) {
                const float* src = emb + (size_t)(ch + 1) * 32 * ND;
                float* dst = sE + ((ch + 1) & 1) * 8192;
                for (int i = tid; i < 2048; i += 256) cp16(dst + i * 4, src + i * 4);
                cp_commit();
                cp_wait1();
            } else {
                cp_wait0();
            }
            __syncthreads();
            for (int i = tid; i < 1024; i += 256) {
                int r = i >> 5, c = i & 31;
                sPb[i] = pbase[(size_t)r * NK + ch * 32 + c];
            }
            __syncthreads();

            const float* bp = sE + (ch & 1) * 8192;
#pragma unroll 4
            for (int c = 0; c < 32; ++c) {
                float p0 = sPb[(w * 4 + 0) * 32 + c];
                float p1 = sPb[(w * 4 + 1) * 32 + c];
                float p2 = sPb[(w * 4 + 2) * 32 + c];
                float p3 = sPb[(w * 4 + 3) * 32 + c];
                const float* er = bp + c * ND + lane;
#pragma unroll
                for (int m = 0; m < 8; ++m) {
                    float ev = er[32 * m];
                    qacc[0][m] = fmaf(p0, ev, qacc[0][m]);
                    qacc[1][m] = fmaf(p1, ev, qacc[1][m]);
                    qacc[2][m] = fmaf(p2, ev, qacc[2][m]);
                    qacc[3][m] = fmaf(p3, ev, qacc[3][m]);
                }
            }
            __syncthreads();
        }
#pragma unroll
        for (int i = 0; i < 4; ++i) {
            int row = r0 + w * 4 + i;
#pragma unroll
            for (int m = 0; m < 8; ++m) {
                int d = lane + 32 * m;
                float qv = qacc[i][m];
                out[OFF_Q + (size_t)row * ND + d] = qv;
                float dz = qv - lat[(size_t)row * ND + d];
                lsum = fmaf(dz, dz, lsum);
            }
        }
        __syncthreads();
    }
#pragma unroll
    for (int off = 16; off; off >>= 1) lsum += __shfl_xor_sync(0xffffffffu, lsum, off);
    if (lane == 0) red8[w] = lsum;
    __syncthreads();
    if (tid == 0) {
        float s = 0.f;
        for (int ww = 0; ww < 8; ++ww) s += red8[ww];
        g_ploss[blockIdx.x] = s;
    }
#endif
}

// ---------------- stage-2 avg_probs reduction ----------------
__global__ void k_red() {
    int g = blockIdx.x;
    for (int c = threadIdx.x; c < NK; c += 256) {
        float s = 0.f;
        for (int r = 0; r < 64; ++r) s += g_pavg[(size_t)(g * 64 + r) * NK + c];
        g_pavg2[g * NK + c] = s;
    }
}

// ---------------- finalize scalars ----------------
__global__ void k_fin(float* __restrict__ out) {
    __shared__ float red[1024];
    int t = threadIdx.x;

    float a = 0.f;
    for (int gg = 0; gg < 32; ++gg) a += g_pavg2[gg * NK + t];
    a *= (1.0f / 65536.0f);
    red[t] = -a * logf(a + 1e-10f);
    __syncthreads();
    for (int s = 512; s; s >>= 1) { if (t < s) red[t] += red[t + s]; __syncthreads(); }
    float ent = red[0];
    __syncthreads();

    red[t] = (t < 512) ? g_ploss[t] : 0.f;
    __syncthreads();
    for (int s = 512; s; s >>= 1) { if (t < s) red[t] += red[t + s]; __syncthreads(); }
    float mse = red[0] * (1.0f / 16777216.0f);
    float vq  = __fadd_rn(__fmul_rn(mse, 0.25f), mse);
    __syncthreads();

    red[t] = g_pmind[t] + g_pmind[t + 1024];
    __syncthreads();
    for (int s = 512; s; s >>= 1) { if (t < s) red[t] += red[t + s]; __syncthreads(); }
    float cm = red[0] * (1.0f / 65536.0f);

    if (t == 0) {
        out[OFF_VQ]  = vq;
        out[OFF_ENT] = ent;
        out[OFF_CM]  = cm;
    }
}

// ---------------- host: tensormap construction ----------------
typedef CUresult (*EncodeFn)(CUtensorMap*, CUtensorMapDataType, cuuint32_t,
                             void*, const cuuint64_t*, const cuuint64_t*,
                             const cuuint32_t*, const cuuint32_t*,
                             CUtensorMapInterleave, CUtensorMapSwizzle,
                             CUtensorMapL2promotion, CUtensorMapFloatOOBfill);

static void make_map(EncodeFn enc, CUtensorMap* m, void* ptr,
                     unsigned long long d0, unsigned long long d1,
                     unsigned long long stride_bytes) {
    cuuint64_t dims[2] = {d0, d1};
    cuuint64_t str[1]  = {stride_bytes};
    cuuint32_t box[2]  = {32u, 256u};
    cuuint32_t es[2]   = {1u, 1u};
    enc(m, CU_TENSOR_MAP_DATA_TYPE_FLOAT32, 2, ptr, dims, str, box, es,
        CU_TENSOR_MAP_INTERLEAVE_NONE, CU_TENSOR_MAP_SWIZZLE_128B,
        CU_TENSOR_MAP_L2_PROMOTION_L2_128B, CU_TENSOR_MAP_FLOAT_OOB_FILL_NONE);
}

// ---------------- launch ----------------
extern "C" void kernel_launch(void* const* d_in, const int* in_sizes, int n_in,
                              void* d_out, int out_size) {
    const float* lat = (const float*)d_in[0];
    const float* emb = (const float*)d_in[1];
    float* out = (float*)d_out;

    // driver entry point for cuTensorMapEncodeTiled (no -lcuda dependency)
    void* fp = nullptr;
    cudaDriverEntryPointQueryResult qr;
    cudaGetDriverEntryPoint("cuTensorMapEncodeTiled", &fp, cudaEnableDefault, &qr);
    EncodeFn enc = (EncodeFn)fp;

    void *pEmbI = nullptr, *pEmbTI = nullptr;
    cudaGetSymbolAddress(&pEmbI, g_embI);
    cudaGetSymbolAddress(&pEmbTI, g_embTI);

    CUtensorMap m1, m2;
    make_map(enc, &m1, pEmbI, 512, 1024, 512ull * 4ull);
    make_map(enc, &m2, pEmbTI, 2048, 256, 2048ull * 4ull);

    cudaFuncSetAttribute(k_gemm1, cudaFuncAttributeMaxDynamicSharedMemorySize, G_SMEM);
    cudaFuncSetAttribute(k_gemm2, cudaFuncAttributeMaxDynamicSharedMemorySize, G_SMEM);

    k_prep2<<<1024, 256>>>(emb);
    k_ee<<<4, 256>>>(emb);
    k_nop<<<1, 32>>>();                 // shifts ncu window onto k_gemm1 (#4)
    k_gemm1<<<512, 256, G_SMEM>>>(lat, m1);
    k_soft<<<2048, 256>>>(lat, emb, out);
    k_gemm2<<<512, 256, G_SMEM>>>(lat, m2, emb, out);
    k_red<<<32, 256>>>();
    k_fin<<<1, 1024>>>(out);
}

// round 14
// speedup vs baseline: 1.1252x; 1.1252x over previous
#include <cuda_runtime.h>
#include <cuda.h>
#include <math.h>
#include <stdint.h>

// ---------------------------------------------------------------------------
// VectorQuantizerLinearSoft — tcgen05 3xTF32, TMA B-loads, 2-stage ring,
// 2 CTAs/SM (R14): cross-CTA coverage of MMA/epilogue bubbles.
// ---------------------------------------------------------------------------

#if defined(__CUDA_ARCH_FEAT_SM103_ALL) || defined(__CUDA_ARCH_FEAT_SM100_ALL)
#define HAS_TC 1
#else
#define HAS_TC 0
#endif

constexpr int NB = 65536;
constexpr int ND = 256;
constexpr int NK = 1024;

constexpr size_t OFF_Q   = 0;
constexpr size_t OFF_VQ  = 16777216;
constexpr size_t OFF_ENT = 16777217;
constexpr size_t OFF_IDX = 16777218;
constexpr size_t OFF_HQ  = 16842754;   // only 8B-aligned
constexpr size_t OFF_P   = 33619970;   // only 8B-aligned
constexpr size_t OFF_CM  = 100728834;

// Scratch (device globals: no allocations allowed)
__device__ float g_G[(size_t)NB * NK];      // 256MB  lat @ emb^T
__device__ float g_eT[ND * NK];             // emb^T full precision (fallback)
__device__ float g_embI[(size_t)NK * 512];  // emb rows, [hi16|lo16] per 16-col block
__device__ float g_embTI[(size_t)ND * 2048];// emb^T rows, [hi16|lo16]
__device__ float g_ee[NK];                  // ||e_j||^2
__device__ float g_pavg[2048 * NK];         // per-soft-CTA colsums of probs
__device__ float g_pavg2[32 * NK];
__device__ float g_ploss[512];              // per-GEMM2-CTA sum (q-z)^2
__device__ float g_pmind[2048];             // per-soft-CTA sum min dist

// ---------------- generic helpers ----------------
__device__ __forceinline__ void cp16(void* smem, const void* gmem) {
    unsigned s = (unsigned)__cvta_generic_to_shared(smem);
    asm volatile("cp.async.cg.shared.global [%0], [%1], 16;\n" :: "r"(s), "l"(gmem));
}
__device__ __forceinline__ void cp_commit() { asm volatile("cp.async.commit_group;\n"); }
__device__ __forceinline__ void cp_wait1()  { asm volatile("cp.async.wait_group 1;\n"); }
__device__ __forceinline__ void cp_wait0()  { asm volatile("cp.async.wait_group 0;\n"); }

__device__ __forceinline__ float tf32hi(float x) {
    uint32_t u; asm("cvt.rna.tf32.f32 %0, %1;" : "=r"(u) : "f"(x));
    return __uint_as_float(u);
}
__device__ __forceinline__ uint32_t sw128(uint32_t off) { return off ^ ((off >> 3) & 0x70); }

// ---------------- tcgen05 / TMA helpers (accelerated pass only) ------------
#if HAS_TC
__device__ __forceinline__ uint32_t smem_u32(const void* p) {
    uint32_t a;
    asm("{ .reg .u64 t; cvta.to.shared.u64 t, %1; cvt.u32.u64 %0, t; }" : "=r"(a) : "l"(p));
    return a;
}
__device__ __forceinline__ uint32_t elect1() {
    uint32_t p;
    asm volatile("{ .reg .pred p; elect.sync _|p, 0xFFFFFFFF; selp.b32 %0, 1, 0, p; }" : "=r"(p));
    return p;
}
// SW128 K-major smem descriptor (SBO=64, LBO=1, layout SW128, Blackwell v1)
__device__ __forceinline__ uint64_t sdesc(uint32_t addr) {
    return 0x4000404000010000ULL | ((uint64_t)(addr >> 4) & 0x3FFF);
}
// idesc: dtype=F32, atype=btype=TF32(2), N=256, M=128, K-major both
constexpr uint32_t IDESC_TF32_N256 =
    (1u << 4) | (2u << 7) | (2u << 10) | ((256u / 8) << 17) | ((128u / 16) << 24);

__device__ __forceinline__ void mma_tf32(uint32_t d, uint64_t ad, uint64_t bd,
                                         uint32_t idesc, bool en) {
    uint32_t e = en ? 1u : 0u;
    asm volatile(
        "{\n\t.reg .pred p;\n\tsetp.ne.u32 p, %5, 0;\n\t"
        "tcgen05.mma.cta_group::1.kind::tf32 [%0], %1, %2, %3, {%4, %4, %4, %4}, p;\n\t}"
        :: "r"(d), "l"(ad), "l"(bd), "r"(idesc), "r"(0u), "r"(e) : "memory");
}

__device__ __forceinline__ void tma2d(uint32_t dst, const CUtensorMap* map,
                                      int x, int y, uint32_t mbar) {
    asm volatile(
        "cp.async.bulk.tensor.2d.shared::cta.global.tile.mbarrier::complete_tx::bytes "
        "[%0], [%1, {%2, %3}], [%4];"
        :: "r"(dst), "l"(map), "r"(x), "r"(y), "r"(mbar) : "memory");
}

#define FENCE_PROXY()     asm volatile("fence.proxy.async.shared::cta;" ::: "memory")
#define TC_ALLOC(sa, n)   asm volatile("tcgen05.alloc.cta_group::1.sync.aligned.shared::cta.b32 [%0], %1;" :: "r"(sa), "r"(n) : "memory")
#define TC_RELINQ()       asm volatile("tcgen05.relinquish_alloc_permit.cta_group::1.sync.aligned;")
#define TC_DEALLOC(t, n)  asm volatile("tcgen05.dealloc.cta_group::1.sync.aligned.b32 %0, %1;" :: "r"(t), "r"(n))
#define TC_COMMIT(mb)     asm volatile("tcgen05.commit.cta_group::1.mbarrier::arrive::one.shared::cluster.b64 [%0];" :: "r"(mb) : "memory")
#define TC_WAIT_LD()      asm volatile("tcgen05.wait::ld.sync.aligned;" ::: "memory")
#define TC_FENCE_AFTER()  asm volatile("tcgen05.fence::after_thread_sync;" ::: "memory")
#define TC_FENCE_BEFORE() asm volatile("tcgen05.fence::before_thread_sync;" ::: "memory")
#define MBAR_INIT(mb, c)  asm volatile("mbarrier.init.shared.b64 [%0], %1;" :: "r"(mb), "r"(c) : "memory")
#define MBAR_INVAL(mb)    asm volatile("mbarrier.inval.shared.b64 [%0];" :: "r"(mb) : "memory")
#define MBAR_EXPECT(mb, n) asm volatile("mbarrier.arrive.expect_tx.shared.b64 _, [%0], %1;" :: "r"(mb), "r"(n) : "memory")

#define MBAR_WAIT(mb, par) do {                                              \
    uint32_t _m = (mb), _p = (par), _d;                                      \
    asm volatile("{\n\t.reg .pred p;\n\t"                                    \
        "mbarrier.try_wait.parity.acquire.cta.shared::cta.b64 p, [%1], %2;\n\t" \
        "selp.b32 %0, 1, 0, p;\n\t}" : "=r"(_d) : "r"(_m), "r"(_p) : "memory"); \
    if (!_d) {                                                               \
        asm volatile("{\n\t.reg .pred P1;\n\t"                               \
            "WL_%=:\n\t"                                                     \
            "mbarrier.try_wait.parity.acquire.cta.shared::cta.b64 P1, [%0], %1, 0x989680;\n\t" \
            "@P1 bra.uni WD_%=;\n\t"                                         \
            "bra.uni WL_%=;\n\t"                                             \
            "WD_%=:\n\t}" :: "r"(_m), "r"(_p) : "memory");                   \
    }                                                                        \
} while (0)

#define LDTM32(r, a)                                                         \
    asm volatile("tcgen05.ld.sync.aligned.32x32b.x32.b32 "                   \
        "{%0,%1,%2,%3,%4,%5,%6,%7,%8,%9,%10,%11,%12,%13,%14,%15,"            \
        "%16,%17,%18,%19,%20,%21,%22,%23,%24,%25,%26,%27,%28,%29,%30,%31}, [%32];" \
        : "=r"((r)[0]), "=r"((r)[1]), "=r"((r)[2]), "=r"((r)[3]),            \
          "=r"((r)[4]), "=r"((r)[5]), "=r"((r)[6]), "=r"((r)[7]),            \
          "=r"((r)[8]), "=r"((r)[9]), "=r"((r)[10]), "=r"((r)[11]),          \
          "=r"((r)[12]), "=r"((r)[13]), "=r"((r)[14]), "=r"((r)[15]),        \
          "=r"((r)[16]), "=r"((r)[17]), "=r"((r)[18]), "=r"((r)[19]),        \
          "=r"((r)[20]), "=r"((r)[21]), "=r"((r)[22]), "=r"((r)[23]),        \
          "=r"((r)[24]), "=r"((r)[25]), "=r"((r)[26]), "=r"((r)[27]),        \
          "=r"((r)[28]), "=r"((r)[29]), "=r"((r)[30]), "=r"((r)[31])         \
        : "r"(a))
#endif  // HAS_TC

// sub-chunk descriptor offsets (16B units) within a [hi64B|lo64B] 128B row:
// terms: hiA*hiB (2 K-steps), loA*hiB (2), hiA*loB (2)
__device__ __constant__ int c_AO[6] = {0, 2, 4, 6, 0, 2};
__device__ __constant__ int c_BO[6] = {0, 2, 0, 2, 4, 6};

// ---------------- prep: interleaved split tables + row norms ---------------
__global__ void k_prep2(const float* __restrict__ emb) {
    int j = blockIdx.x;  // 0..1023
    int cb = j >> 4, tb = j & 15;
    for (int d = threadIdx.x; d < 256; d += 256) {
        float v = emb[(size_t)j * ND + d];
        float h = tf32hi(v);
        g_eT[(size_t)d * NK + j] = v;
        g_embTI[(size_t)d * 2048 + cb * 32 + tb]      = h;
        g_embTI[(size_t)d * 2048 + cb * 32 + 16 + tb] = __fsub_rn(v, h);
    }
    for (int t = threadIdx.x; t < 512; t += 256) {
        int c = t >> 5, u = t & 31;
        float v = emb[(size_t)j * ND + c * 16 + (u & 15)];
        float h = tf32hi(v);
        g_embI[(size_t)j * 512 + t] = (u < 16) ? h : __fsub_rn(v, h);
    }
}

__global__ void k_ee(const float* __restrict__ emb) {
    int warp = (blockIdx.x * blockDim.x + threadIdx.x) >> 5;
    int lane = threadIdx.x & 31;
    for (int rr = 0; rr < 32; ++rr) {
        int row = warp * 32 + rr;
        float s = 0.f;
#pragma unroll
        for (int k = 0; k < 8; ++k) {
            float v = emb[(size_t)row * ND + lane + 32 * k];
            s = fmaf(v, v, s);
        }
#pragma unroll
        for (int off = 16; off; off >>= 1) s += __shfl_xor_sync(0xffffffffu, s, off);
        if (lane == 0) g_ee[row] = s;
    }
}

// ---------------- profiler window shim (keeps k_gemm1 at launch #4) --------
__global__ void k_nop() {}

// ---------------- GEMM kernels: stage = A(16K) + B(32K) = 48K, 2 stages ----
// smem: [0,4) tmem ptr, [8,24) mma bars, [40,56) tma bars, [80,112) red
constexpr int STG_SZ = 49152;
constexpr int G_SMEM = 1024 + 2 * STG_SZ;   // 99328 per CTA -> 2 CTAs/SM
constexpr int MB_MMA = 8, MB_TMA = 40;

__global__ void __launch_bounds__(256, 2)
k_gemm1(const float* __restrict__ lat,
        const __grid_constant__ CUtensorMap tmB) {
#if HAS_TC
    extern __shared__ char smem[];
    uint32_t sbase = smem_u32(smem);
    const int tid = threadIdx.x, wid = tid >> 5;
    const int row0 = blockIdx.x * 128;

    if (wid == 0) { TC_ALLOC(sbase, 256); TC_RELINQ(); }
    if (tid == 0)
        for (int b = 0; b < 2; ++b) {
            MBAR_INIT(sbase + MB_MMA + b * 8, 1);
            MBAR_INIT(sbase + MB_TMA + b * 8, 1);
        }
    __syncthreads();
    uint32_t tmem;
    asm volatile("ld.shared.b32 %0, [%1];" : "=r"(tmem) : "r"(sbase));

    const float* latb = lat + (size_t)row0 * ND;

    auto prep_load = [&](int gp, float4* v) {
        int c = gp & 15;
#pragma unroll
        for (int it = 0; it < 2; ++it) {
            int t = tid + it * 256;
            int r = t >> 2, c4 = t & 3;
            v[it] = *(const float4*)(latb + (size_t)r * ND + c * 16 + c4 * 4);
        }
    };
    auto prep_storeA = [&](int gp, const float4* v) {
        char* st = smem + 1024 + (gp & 1) * STG_SZ;
#pragma unroll
        for (int it = 0; it < 2; ++it) {
            int t = tid + it * 256;
            int r = t >> 2, c4 = t & 3;
            float4 vv = v[it];
            float4 h = make_float4(tf32hi(vv.x), tf32hi(vv.y), tf32hi(vv.z), tf32hi(vv.w));
            float4 l = make_float4(__fsub_rn(vv.x, h.x), __fsub_rn(vv.y, h.y),
                                   __fsub_rn(vv.z, h.z), __fsub_rn(vv.w, h.w));
            *(float4*)(st + sw128(r * 128 + c4 * 16))      = h;
            *(float4*)(st + sw128(r * 128 + 64 + c4 * 16)) = l;
        }
        FENCE_PROXY();
    };
    auto issue_tma = [&](int gp) {
        if (tid == 0) {
            uint32_t mb = sbase + MB_TMA + (gp & 1) * 8;
            MBAR_EXPECT(mb, 32768u);
            tma2d(sbase + 1024 + (gp & 1) * STG_SZ + 16384, &tmB,
                  (gp & 15) * 32, (gp >> 4) * 256, mb);
        }
    };

    auto epilogue = [&](int q) {
        int wg = tid >> 7, w4 = (tid >> 5) & 3, lane = tid & 31;
        int row = row0 + w4 * 32 + lane;
#pragma unroll 1
        for (int b = 0; b < 4; ++b) {
            uint32_t r[32];
            LDTM32(r, tmem + wg * 128 + b * 32);
            TC_WAIT_LD();
            float4* gp = (float4*)&g_G[(size_t)row * NK + q * 256 + wg * 128 + b * 32];
#pragma unroll
            for (int c4 = 0; c4 < 8; ++c4)
                gp[c4] = make_float4(__uint_as_float(r[c4 * 4 + 0]),
                                     __uint_as_float(r[c4 * 4 + 1]),
                                     __uint_as_float(r[c4 * 4 + 2]),
                                     __uint_as_float(r[c4 * 4 + 3]));
        }
        TC_FENCE_BEFORE();
    };

    {   // prologue: chunks 0, 1
        float4 v[2];
        prep_load(0, v); prep_storeA(0, v); issue_tma(0);
        prep_load(1, v); prep_storeA(1, v); issue_tma(1);
    }

    for (int g = 0; g < 64; ++g) {
        const bool doP = (g + 2 < 64);
        float4 pf[2];
        if (doP) prep_load(g + 2, pf);
        MBAR_WAIT(sbase + MB_TMA + (g & 1) * 8, (uint32_t)((g >> 1) & 1));
        __syncthreads();           // D free (epilogue done) + stage visible
        int c = g & 15;
        if (wid == 0) {
            if (elect1()) {
                uint32_t sa = sbase + 1024 + (g & 1) * STG_SZ;
                uint64_t ad = sdesc(sa);
                uint64_t bd = sdesc(sa + 16384);
#pragma unroll
                for (int i = 0; i < 6; ++i)
                    mma_tf32(tmem, ad + c_AO[i], bd + c_BO[i], IDESC_TF32_N256,
                             (c > 0) || (i > 0));
                TC_COMMIT(sbase + MB_MMA + (g & 1) * 8);
            }
        }
        // 2-stage ring: stage g&1 is reused by chunk g+2 -> must wait own mma
        MBAR_WAIT(sbase + MB_MMA + (g & 1) * 8, (uint32_t)((g >> 1) & 1));
        if (c == 15) {             // pass complete: drain D before next pass
            TC_FENCE_AFTER();
            epilogue(g >> 4);
        }
        if (doP) { prep_storeA(g + 2, pf); issue_tma(g + 2); }
    }
    __syncthreads();
    if (tid == 0)
        for (int b = 0; b < 2; ++b) {
            MBAR_INVAL(sbase + MB_MMA + b * 8);
            MBAR_INVAL(sbase + MB_TMA + b * 8);
        }
    __syncthreads();
    if (wid == 0) TC_DEALLOC(tmem, 256);
#else
    // ---------------- FFMA fallback (R4 GEMM1 structure) ----------------
    extern __shared__ float smf[];
    float* sZ = smf;
    float* sE = smf + 8192;
    const int tid = threadIdx.x, w = tid >> 5, lane = tid & 31;
    const int row0 = blockIdx.x * 128;

    for (int st = 0; st < 4; ++st) {
        const int r0 = row0 + st * 32;
        for (int i = tid; i < 4096; i += 256) cp16(sE + i * 4, g_eT + i * 4);
        cp_commit();
        for (int i = tid; i < 2048; i += 256)
            ((float4*)sZ)[i] = ((const float4*)(lat + (size_t)r0 * ND))[i];
        __syncthreads();

        float acc[4][32];
#pragma unroll
        for (int i = 0; i < 4; ++i)
#pragma unroll
            for (int j = 0; j < 32; ++j) acc[i][j] = 0.f;

#pragma unroll 1
        for (int ch = 0; ch < 16; ++ch) {
            if (ch < 15) {
                const float* src = g_eT + (size_t)(ch + 1) * 16 * NK;
                float* dst = sE + ((ch + 1) & 1) * 16384;
                for (int i = tid; i < 4096; i += 256) cp16(dst + i * 4, src + i * 4);
                cp_commit();
                cp_wait1();
            } else {
                cp_wait0();
            }
            __syncthreads();

            const float* bufp = sE + (ch & 1) * 16384;
            const float* zrow = sZ + (w * 4) * ND + ch * 16;
#pragma unroll 4
            for (int kk = 0; kk < 16; ++kk) {
                float z0 = zrow[kk];
                float z1 = zrow[256 + kk];
                float z2 = zrow[512 + kk];
                float z3 = zrow[768 + kk];
                const float* er = bufp + kk * NK + lane;
#pragma unroll
                for (int j = 0; j < 32; ++j) {
                    float ev = er[j * 32];
                    acc[0][j] = fmaf(z0, ev, acc[0][j]);
                    acc[1][j] = fmaf(z1, ev, acc[1][j]);
                    acc[2][j] = fmaf(z2, ev, acc[2][j]);
                    acc[3][j] = fmaf(z3, ev, acc[3][j]);
                }
            }
            __syncthreads();
        }
#pragma unroll
        for (int i = 0; i < 4; ++i) {
            float* gp = &g_G[(size_t)(r0 + w * 4 + i) * NK];
#pragma unroll
            for (int j = 0; j < 32; ++j) gp[lane + 32 * j] = acc[i][j];
        }
        __syncthreads();
    }
#endif
}

// ---------------- k_soft: dist/argmin(+exact refine)/softmax + partials ----
__global__ void __launch_bounds__(256, 2)
k_soft(const float* __restrict__ lat, const float* __restrict__ emb,
       float* __restrict__ out) {
    __shared__ float sX[8 * NK];
    __shared__ float s_mind[32];
    __shared__ int   s_idx[32];

    const int cta = blockIdx.x, row0 = cta * 32;
    const int tid = threadIdx.x, w = tid >> 5, lane = tid & 31;

    float csum[32];
#pragma unroll
    for (int j = 0; j < 32; ++j) csum[j] = 0.f;

#pragma unroll 1
    for (int i = 0; i < 4; ++i) {
        const int r = row0 + w * 4 + i;
        const float* zr = lat + (size_t)r * ND;

        float zz = 0.f;
#pragma unroll
        for (int k = 0; k < 8; ++k) { float v = zr[lane + 32 * k]; zz = fmaf(v, v, zz); }
#pragma unroll
        for (int off = 16; off; off >>= 1) zz += __shfl_xor_sync(0xffffffffu, zz, off);

        float g[32];
        const float* gr = g_G + (size_t)r * NK;
#pragma unroll
        for (int j = 0; j < 32; ++j) g[j] = gr[lane + 32 * j];

        float dmin = 3.4e38f;
#pragma unroll
        for (int j = 0; j < 32; ++j) {
            float ee = __ldg(&g_ee[lane + 32 * j]);
            float di = __fsub_rn(__fadd_rn(zz, ee), __fmul_rn(2.0f, g[j]));
            g[j] = di;
            dmin = fminf(dmin, di);
        }
#pragma unroll
        for (int off = 16; off; off >>= 1)
            dmin = fminf(dmin, __shfl_xor_sync(0xffffffffu, dmin, off));

        // exact-FFMA refinement of argmin (tensor dist error << 1e-4)
        {
            float thr = dmin + 1e-4f;
            float bd = 3.4e38f;
            int   bi = NK;
#pragma unroll 1
            for (int j = 0; j < 32; ++j) {
                unsigned m = __ballot_sync(0xffffffffu, g[j] < thr);
                while (m) {
                    int src = __ffs(m) - 1;
                    m &= m - 1;
                    int col = src + 32 * j;
                    const float* er = emb + (size_t)col * ND;
                    float s = 0.f;
#pragma unroll
                    for (int k = 0; k < 8; ++k)
                        s = fmaf(zr[lane + 32 * k], __ldg(&er[lane + 32 * k]), s);
#pragma unroll
                    for (int off = 16; off; off >>= 1)
                        s += __shfl_xor_sync(0xffffffffu, s, off);
                    float dc = __fsub_rn(__fadd_rn(zz, __ldg(&g_ee[col])),
                                         __fmul_rn(2.0f, s));
                    if (dc < bd) { bd = dc; bi = col; }
                }
            }
            if (lane == 0) { s_mind[w * 4 + i] = bd; s_idx[w * 4 + i] = bi; }
        }

        float ssum = 0.f;
#pragma unroll
        for (int j = 0; j < 32; ++j) {
            float pv = __expf(-10.0f * (g[j] - dmin));
            g[j] = pv;
            ssum += pv;
        }
#pragma unroll
        for (int off = 16; off; off >>= 1) ssum += __shfl_xor_sync(0xffffffffu, ssum, off);
        float rinv = 1.0f / ssum;
        float* pout = out + OFF_P + (size_t)r * NK;
#pragma unroll
        for (int j = 0; j < 32; ++j) {
            float p = g[j] * rinv;
            pout[lane + 32 * j] = p;
            csum[j] += p;
        }
    }

#pragma unroll
    for (int j = 0; j < 32; ++j) sX[w * NK + lane + 32 * j] = csum[j];
    __syncthreads();

    for (int c = tid; c < NK; c += 256) {
        float s = 0.f;
#pragma unroll
        for (int ww = 0; ww < 8; ++ww) s += sX[ww * NK + c];
        g_pavg[(size_t)cta * NK + c] = s;
    }
    if (tid == 0) {
        float s = 0.f;
        for (int r = 0; r < 32; ++r) s += s_mind[r];
        g_pmind[cta] = s;
    }
    if (tid < 32) out[OFF_IDX + row0 + tid] = (float)s_idx[tid];

    for (int i = tid; i < 32 * ND / 2; i += 256) {
        int r = i >> 7, d2 = i & 127;
        float2 v = ((const float2*)(emb + (size_t)s_idx[r] * ND))[d2];
        ((float2*)(out + OFF_HQ + (size_t)row0 * ND))[i] = v;
    }
}

// ---------------- GEMM2: Q = P @ emb (M=128/CTA, N=256, 64 K-blocks) -------
__global__ void __launch_bounds__(256, 2)
k_gemm2(const float* __restrict__ lat,
        const __grid_constant__ CUtensorMap tmB,
        const float* __restrict__ emb, float* __restrict__ out) {
    (void)emb;
#if HAS_TC
    extern __shared__ char smem[];
    uint32_t sbase = smem_u32(smem);
    const int tid = threadIdx.x, wid = tid >> 5;
    const int row0 = blockIdx.x * 128;

    if (wid == 0) { TC_ALLOC(sbase, 256); TC_RELINQ(); }
    if (tid == 0)
        for (int b = 0; b < 2; ++b) {
            MBAR_INIT(sbase + MB_MMA + b * 8, 1);
            MBAR_INIT(sbase + MB_TMA + b * 8, 1);
        }
    __syncthreads();
    uint32_t tmem;
    asm volatile("ld.shared.b32 %0, [%1];" : "=r"(tmem) : "r"(sbase));

    const float* pbase = out + OFF_P + (size_t)row0 * NK;

    auto prep_load = [&](int gp, float4* v) {
#pragma unroll
        for (int it = 0; it < 2; ++it) {
            int t = tid + it * 256;
            int r = t >> 2, c4 = t & 3;
            const float* src = pbase + (size_t)r * NK + gp * 16 + c4 * 4;
            float2 v01 = *(const float2*)(src);
            float2 v23 = *(const float2*)(src + 2);
            v[it] = make_float4(v01.x, v01.y, v23.x, v23.y);
        }
    };
    auto prep_storeA = [&](int gp, const float4* v) {
        char* st = smem + 1024 + (gp & 1) * STG_SZ;
#pragma unroll
        for (int it = 0; it < 2; ++it) {
            int t = tid + it * 256;
            int r = t >> 2, c4 = t & 3;
            float4 vv = v[it];
            float4 h = make_float4(tf32hi(vv.x), tf32hi(vv.y), tf32hi(vv.z), tf32hi(vv.w));
            float4 l = make_float4(__fsub_rn(vv.x, h.x), __fsub_rn(vv.y, h.y),
                                   __fsub_rn(vv.z, h.z), __fsub_rn(vv.w, h.w));
            *(float4*)(st + sw128(r * 128 + c4 * 16))      = h;
            *(float4*)(st + sw128(r * 128 + 64 + c4 * 16)) = l;
        }
        FENCE_PROXY();
    };
    auto issue_tma = [&](int gp) {
        if (tid == 0) {
            uint32_t mb = sbase + MB_TMA + (gp & 1) * 8;
            MBAR_EXPECT(mb, 32768u);
            tma2d(sbase + 1024 + (gp & 1) * STG_SZ + 16384, &tmB,
                  gp * 32, 0, mb);
        }
    };

    {   // prologue
        float4 v[2];
        prep_load(0, v); prep_storeA(0, v); issue_tma(0);
        prep_load(1, v); prep_storeA(1, v); issue_tma(1);
    }

    for (int g = 0; g < 64; ++g) {
        const bool doP = (g + 2 < 64);
        float4 pf[2];
        if (doP) prep_load(g + 2, pf);
        MBAR_WAIT(sbase + MB_TMA + (g & 1) * 8, (uint32_t)((g >> 1) & 1));
        __syncthreads();
        if (wid == 0) {
            if (elect1()) {
                uint32_t sa = sbase + 1024 + (g & 1) * STG_SZ;
                uint64_t ad = sdesc(sa);
                uint64_t bd = sdesc(sa + 16384);
#pragma unroll
                for (int i = 0; i < 6; ++i)
                    mma_tf32(tmem, ad + c_AO[i], bd + c_BO[i], IDESC_TF32_N256,
                             (g > 0) || (i > 0));
                TC_COMMIT(sbase + MB_MMA + (g & 1) * 8);
            }
        }
        MBAR_WAIT(sbase + MB_MMA + (g & 1) * 8, (uint32_t)((g >> 1) & 1));
        if (doP) { prep_storeA(g + 2, pf); issue_tma(g + 2); }
    }
    TC_FENCE_AFTER();

    // epilogue: D[128 lanes][256 cols] -> q, loss partial
    {
        int wg = tid >> 7, w4 = (tid >> 5) & 3, lane = tid & 31;
        int row = row0 + w4 * 32 + lane;
        float lp = 0.f;
#pragma unroll 1
        for (int b = 0; b < 4; ++b) {
            uint32_t r[32];
            LDTM32(r, tmem + wg * 128 + b * 32);
            TC_WAIT_LD();
            int cb = wg * 128 + b * 32;
            float4* qp = (float4*)(out + OFF_Q + (size_t)row * ND + cb);
            const float4* lt = (const float4*)(lat + (size_t)row * ND + cb);
#pragma unroll
            for (int c4 = 0; c4 < 8; ++c4) {
                float4 q = make_float4(__uint_as_float(r[c4 * 4 + 0]),
                                       __uint_as_float(r[c4 * 4 + 1]),
                                       __uint_as_float(r[c4 * 4 + 2]),
                                       __uint_as_float(r[c4 * 4 + 3]));
                float4 l = lt[c4];
                qp[c4] = q;
                float d0 = q.x - l.x, d1 = q.y - l.y, d2 = q.z - l.z, d3 = q.w - l.w;
                lp = fmaf(d0, d0, lp); lp = fmaf(d1, d1, lp);
                lp = fmaf(d2, d2, lp); lp = fmaf(d3, d3, lp);
            }
        }
        TC_FENCE_BEFORE();
#pragma unroll
        for (int off = 16; off; off >>= 1) lp += __shfl_xor_sync(0xffffffffu, lp, off);
        float* red = (float*)(smem + 80);
        if ((tid & 31) == 0) red[tid >> 5] = lp;
        __syncthreads();
        if (tid == 0) {
            float s = 0.f;
            for (int ww = 0; ww < 8; ++ww) s += red[ww];
            g_ploss[blockIdx.x] = s;
        }
    }
    if (tid == 0)
        for (int b = 0; b < 2; ++b) {
            MBAR_INVAL(sbase + MB_MMA + b * 8);
            MBAR_INVAL(sbase + MB_TMA + b * 8);
        }
    __syncthreads();
    if (wid == 0) TC_DEALLOC(tmem, 256);
#else
    // ---------------- FFMA fallback (R4 GEMM2 structure) ----------------
    extern __shared__ float smf[];
    float* sE  = smf;
    float* sPb = smf + 16384;
    __shared__ float red8[8];
    const int tid = threadIdx.x, w = tid >> 5, lane = tid & 31;
    const int row0 = blockIdx.x * 128;
    float lsum = 0.f;

    for (int st = 0; st < 4; ++st) {
        const int r0 = row0 + st * 32;
        const float* pbase = out + OFF_P + (size_t)r0 * NK;

        float qacc[4][8];
#pragma unroll
        for (int i = 0; i < 4; ++i)
#pragma unroll
            for (int m = 0; m < 8; ++m) qacc[i][m] = 0.f;

        for (int i = tid; i < 2048; i += 256) cp16(sE + i * 4, emb + i * 4);
        cp_commit();

#pragma unroll 1
        for (int ch = 0; ch < 32; ++ch) {
            if (ch < 31) {
                const float* src = emb + (size_t)(ch + 1) * 32 * ND;
                float* dst = sE + ((ch + 1) & 1) * 8192;
                for (int i = tid; i < 2048; i += 256) cp16(dst + i * 4, src + i * 4);
                cp_commit();
                cp_wait1();
            } else {
                cp_wait0();
            }
            __syncthreads();
            for (int i = tid; i < 1024; i += 256) {
                int r = i >> 5, c = i & 31;
                sPb[i] = pbase[(size_t)r * NK + ch * 32 + c];
            }
            __syncthreads();

            const float* bp = sE + (ch & 1) * 8192;
#pragma unroll 4
            for (int c = 0; c < 32; ++c) {
                float p0 = sPb[(w * 4 + 0) * 32 + c];
                float p1 = sPb[(w * 4 + 1) * 32 + c];
                float p2 = sPb[(w * 4 + 2) * 32 + c];
                float p3 = sPb[(w * 4 + 3) * 32 + c];
                const float* er = bp + c * ND + lane;
#pragma unroll
                for (int m = 0; m < 8; ++m) {
                    float ev = er[32 * m];
                    qacc[0][m] = fmaf(p0, ev, qacc[0][m]);
                    qacc[1][m] = fmaf(p1, ev, qacc[1][m]);
                    qacc[2][m] = fmaf(p2, ev, qacc[2][m]);
                    qacc[3][m] = fmaf(p3, ev, qacc[3][m]);
                }
            }
            __syncthreads();
        }
#pragma unroll
        for (int i = 0; i < 4; ++i) {
            int row = r0 + w * 4 + i;
#pragma unroll
            for (int m = 0; m < 8; ++m) {
                int d = lane + 32 * m;
                float qv = qacc[i][m];
                out[OFF_Q + (size_t)row * ND + d] = qv;
                float dz = qv - lat[(size_t)row * ND + d];
                lsum = fmaf(dz, dz, lsum);
            }
        }
        __syncthreads();
    }
#pragma unroll
    for (int off = 16; off; off >>= 1) lsum += __shfl_xor_sync(0xffffffffu, lsum, off);
    if (lane == 0) red8[w] = lsum;
    __syncthreads();
    if (tid == 0) {
        float s = 0.f;
        for (int ww = 0; ww < 8; ++ww) s += red8[ww];
        g_ploss[blockIdx.x] = s;
    }
#endif
}

// ---------------- stage-2 avg_probs reduction ----------------
__global__ void k_red() {
    int g = blockIdx.x;
    for (int c = threadIdx.x; c < NK; c += 256) {
        float s = 0.f;
        for (int r = 0; r < 64; ++r) s += g_pavg[(size_t)(g * 64 + r) * NK + c];
        g_pavg2[g * NK + c] = s;
    }
}

// ---------------- finalize scalars ----------------
__global__ void k_fin(float* __restrict__ out) {
    __shared__ float red[1024];
    int t = threadIdx.x;

    float a = 0.f;
    for (int gg = 0; gg < 32; ++gg) a += g_pavg2[gg * NK + t];
    a *= (1.0f / 65536.0f);
    red[t] = -a * logf(a + 1e-10f);
    __syncthreads();
    for (int s = 512; s; s >>= 1) { if (t < s) red[t] += red[t + s]; __syncthreads(); }
    float ent = red[0];
    __syncthreads();

    red[t] = (t < 512) ? g_ploss[t] : 0.f;
    __syncthreads();
    for (int s = 512; s; s >>= 1) { if (t < s) red[t] += red[t + s]; __syncthreads(); }
    float mse = red[0] * (1.0f / 16777216.0f);
    float vq  = __fadd_rn(__fmul_rn(mse, 0.25f), mse);
    __syncthreads();

    red[t] = g_pmind[t] + g_pmind[t + 1024];
    __syncthreads();
    for (int s = 512; s; s >>= 1) { if (t < s) red[t] += red[t + s]; __syncthreads(); }
    float cm = red[0] * (1.0f / 65536.0f);

    if (t == 0) {
        out[OFF_VQ]  = vq;
        out[OFF_ENT] = ent;
        out[OFF_CM]  = cm;
    }
}

// ---------------- host: tensormap construction ----------------
typedef CUresult (*EncodeFn)(CUtensorMap*, CUtensorMapDataType, cuuint32_t,
                             void*, const cuuint64_t*, const cuuint64_t*,
                             const cuuint32_t*, const cuuint32_t*,
                             CUtensorMapInterleave, CUtensorMapSwizzle,
                             CUtensorMapL2promotion, CUtensorMapFloatOOBfill);

static void make_map(EncodeFn enc, CUtensorMap* m, void* ptr,
                     unsigned long long d0, unsigned long long d1,
                     unsigned long long stride_bytes) {
    cuuint64_t dims[2] = {d0, d1};
    cuuint64_t str[1]  = {stride_bytes};
    cuuint32_t box[2]  = {32u, 256u};
    cuuint32_t es[2]   = {1u, 1u};
    enc(m, CU_TENSOR_MAP_DATA_TYPE_FLOAT32, 2, ptr, dims, str, box, es,
        CU_TENSOR_MAP_INTERLEAVE_NONE, CU_TENSOR_MAP_SWIZZLE_128B,
        CU_TENSOR_MAP_L2_PROMOTION_L2_128B, CU_TENSOR_MAP_FLOAT_OOB_FILL_NONE);
}

// ---------------- launch ----------------
extern "C" void kernel_launch(void* const* d_in, const int* in_sizes, int n_in,
                              void* d_out, int out_size) {
    const float* lat = (const float*)d_in[0];
    const float* emb = (const float*)d_in[1];
    float* out = (float*)d_out;

    // driver entry point for cuTensorMapEncodeTiled (no -lcuda dependency)
    void* fp = nullptr;
    cudaDriverEntryPointQueryResult qr;
    cudaGetDriverEntryPoint("cuTensorMapEncodeTiled", &fp, cudaEnableDefault, &qr);
    EncodeFn enc = (EncodeFn)fp;

    void *pEmbI = nullptr, *pEmbTI = nullptr;
    cudaGetSymbolAddress(&pEmbI, g_embI);
    cudaGetSymbolAddress(&pEmbTI, g_embTI);

    CUtensorMap m1, m2;
    make_map(enc, &m1, pEmbI, 512, 1024, 512ull * 4ull);
    make_map(enc, &m2, pEmbTI, 2048, 256, 2048ull * 4ull);

    cudaFuncSetAttribute(k_gemm1, cudaFuncAttributeMaxDynamicSharedMemorySize, G_SMEM);
    cudaFuncSetAttribute(k_gemm2, cudaFuncAttributeMaxDynamicSharedMemorySize, G_SMEM);

    k_prep2<<<1024, 256>>>(emb);
    k_ee<<<4, 256>>>(emb);
    k_nop<<<1, 32>>>();                 // keeps k_gemm1 at launch #4 for ncu
    k_gemm1<<<512, 256, G_SMEM>>>(lat, m1);
    k_soft<<<2048, 256>>>(lat, emb, out);
    k_gemm2<<<512, 256, G_SMEM>>>(lat, m2, emb, out);
    k_red<<<32, 256>>>();
    k_fin<<<1, 1024>>>(out);
}